// round 10
// baseline (speedup 1.0000x reference)
#include <cuda_runtime.h>
#include <math.h>

#define Bb 16
#define II 512
#define HH 1024
#define BH (Bb*HH)            // 16384
#define NKC 6                 // K-chunks of 256 columns

// Output offsets (floats): h, c, e_w_ix, e_w_ih, e_b_i, e_w_fx, e_w_fh, e_b_f, e_w_cx, e_w_ch, e_b_c
#define OFF_H     0
#define OFF_C     16384
#define OFF_EWIX  32768
#define OFF_EWIH  8421376
#define OFF_EBI   25198592
#define OFF_EWFX  25214976
#define OFF_EWFH  33603584
#define OFF_EBF   50380800
#define OFF_EWCX  50397184
#define OFF_EWCH  58785792
#define OFF_EBC   75563008

// Scratch (no allocation allowed)
__device__ float g_part[NKC][4 * BH];   // partial pre-activations per K-chunk

struct GatePtrs {
    const float* wx[4];
    const float* wh[4];
};

#define FMA4(A, Z, ACC)                         \
    ACC = fmaf((A).x, (Z).x, ACC);              \
    ACC = fmaf((A).y, (Z).y, ACC);              \
    ACC = fmaf((A).z, (Z).z, ACC);              \
    ACC = fmaf((A).w, (Z).w, ACC);

// ---------------------------------------------------------------------------
// Kernel 1: gate pre-activation partials — no smem, no syncthreads, and now
// sized for 32 resident warps/SM: 2 j-rows x 16 batches per warp (32 accs,
// 16 weight regs -> ~64 total regs, launch_bounds(128,8)).
// grid = (HH/8, 4 gates, 6 K-chunks of 256 cols), block = 128 (4 warps).
// ---------------------------------------------------------------------------
__global__ __launch_bounds__(128, 8) void gates_kernel(
    const float* __restrict__ x, const float* __restrict__ h_last, GatePtrs p)
{
    const int tid  = threadIdx.x;
    const int warp = tid >> 5;
    const int lane = tid & 31;
    const int kc   = blockIdx.z;
    const int g    = blockIdx.y;
    const int j0   = blockIdx.x * 8 + warp * 2;

    const float* wbase = (kc < 2) ? p.wx[g] : p.wh[g];
    const int rowlen   = (kc < 2) ? II : HH;
    const int koff     = (kc < 2) ? kc * 256 : (kc - 2) * 256;

    const float4* zsrc = (kc < 2) ? (const float4*)x : (const float4*)h_last;
    const int rowf4    = (kc < 2) ? (II / 4) : (HH / 4);
    const int zoff     = (kc < 2) ? kc * 64 : (kc - 2) * 64;

    // Front-batch weight loads: 4 independent LDG.128 (2 rows x 2 its).
    float4 w[2][2];
#pragma unroll
    for (int r = 0; r < 2; r++) {
        const float4* wr = (const float4*)(wbase + (size_t)(j0 + r) * rowlen + koff);
#pragma unroll
        for (int it = 0; it < 2; it++)
            w[r][it] = wr[it * 32 + lane];
    }

    // a[m]: m = jj*16 + b (jj in 0..1)
    float a[32];
#pragma unroll
    for (int m = 0; m < 32; m++) a[m] = 0.f;

#pragma unroll
    for (int it = 0; it < 2; it++) {
        const int k4 = zoff + it * 32 + lane;
#pragma unroll
        for (int b = 0; b < Bb; b++) {
            float4 z = __ldg(zsrc + b * rowf4 + k4);
            FMA4(w[0][it], z, a[b]);
            FMA4(w[1][it], z, a[16 + b]);
        }
    }

    // Multi-value butterfly reduction: 32 values -> 1 per lane (31 shuffles).
#pragma unroll
    for (int k = 0; k < 5; k++) {
        const int d = 1 << k;
        const int n = 32 >> k;
        const bool hi = (lane >> k) & 1;
#pragma unroll
        for (int m = 0; m < 16; m++) {
            if (m < n / 2) {
                float mine = hi ? a[m] : a[m + n / 2];
                float got  = __shfl_xor_sync(0xffffffffu, mine, d);
                a[m] = (hi ? a[m + n / 2] : a[m]) + got;
            }
        }
    }

    // lane holds value index bitrev5(lane): v = jj*16 + b
    const unsigned rev = __brev((unsigned)lane) >> 27;
    const int jj = rev >> 4;
    const int b  = rev & 15;
    g_part[kc][g * BH + b * HH + j0 + jj] = a[0];
}

// ---------------------------------------------------------------------------
// Kernel 2: fused pointwise + HBM-bound trace update (unchanged; measured
// 5.93 TB/s three rounds running — at the mixed R/W HBM ceiling).
// ---------------------------------------------------------------------------
#define JT 16

__global__ __launch_bounds__(256) void trace_kernel(
    const float* __restrict__ x, const float* __restrict__ h_last,
    const float* __restrict__ c_last,
    const float* __restrict__ b_i, const float* __restrict__ b_f,
    const float* __restrict__ b_o, const float* __restrict__ b_c,
    const float* __restrict__ eb_i, const float* __restrict__ eb_f,
    const float* __restrict__ eb_c,
    const float* __restrict__ e_ix, const float* __restrict__ e_ih,
    const float* __restrict__ e_fx, const float* __restrict__ e_fh,
    const float* __restrict__ e_cx, const float* __restrict__ e_ch,
    float* __restrict__ out)
{
    __shared__ float4 sx[II / 4];   // 2KB
    __shared__ float4 sh[HH / 4];   // 4KB
    __shared__ float4 scf[JT];

    const int tid = threadIdx.x;
    const int b   = blockIdx.y;
    const int j0  = blockIdx.x * JT;

    if (tid < 128) sx[tid] = ((const float4*)(x + b * II))[tid];
    sh[tid] = ((const float4*)(h_last + b * HH))[tid];

    if (tid < JT) {
        const int j   = j0 + tid;
        const int idx = b * HH + j;

        float pi = b_i[j], pf = b_f[j], po = b_o[j], pc = b_c[j];
#pragma unroll
        for (int c = 0; c < NKC; c++) {
            pi += g_part[c][0 * BH + idx];
            pf += g_part[c][1 * BH + idx];
            po += g_part[c][2 * BH + idx];
            pc += g_part[c][3 * BH + idx];
        }

        float i  = 1.f / (1.f + expf(-pi));
        float f  = 1.f / (1.f + expf(-pf));
        float o  = 1.f / (1.f + expf(-po));
        float ch = tanhf(pc);
        float cl = c_last[idx];

        float c = fmaf(f, cl, i * ch);
        float h = o * c;
        float di  = i * (1.f - i);
        float df  = f * (1.f - f);
        float dch = 1.f - ch * ch;
        float ai = di * ch;
        float af = df * cl;
        float ac = dch * i;

        out[OFF_H + idx]   = h;
        out[OFF_C + idx]   = c;
        out[OFF_EBI + idx] = fmaf(eb_i[idx], f, ai);
        out[OFF_EBF + idx] = fmaf(eb_f[idx], f, af);
        out[OFF_EBC + idx] = fmaf(eb_c[idx], f, ac);
        scf[tid] = make_float4(f, ai, af, ac);
    }
    __syncthreads();

    const size_t baseH = (size_t)(b * HH + j0) * (HH / 4);
    const size_t baseI = (size_t)(b * HH + j0) * (II / 4);

    const float4 hv = sh[tid];
    const float4 xv = sx[tid & 127];
    const int xsel = tid >> 7;

#define TRACE_H(SRC, OFF, SEL)                                              \
    {                                                                       \
        const float4* ein = (const float4*)(SRC) + baseH;                   \
        float4* eo = (float4*)(out + (OFF)) + baseH;                        \
        _Pragma("unroll")                                                   \
        for (int it = 0; it < JT; it++) {                                   \
            const int t = tid + it * 256;                                   \
            float4 cf = scf[it];                                            \
            float fv = cf.x, aa = cf.SEL;                                   \
            float4 e  = __ldcs(ein + t);                                    \
            float4 rr;                                                      \
            rr.x = fmaf(e.x, fv, aa * hv.x);                                \
            rr.y = fmaf(e.y, fv, aa * hv.y);                                \
            rr.z = fmaf(e.z, fv, aa * hv.z);                                \
            rr.w = fmaf(e.w, fv, aa * hv.w);                                \
            __stcs(eo + t, rr);                                             \
        }                                                                   \
    }

#define TRACE_X(SRC, OFF, SEL)                                              \
    {                                                                       \
        const float4* ein = (const float4*)(SRC) + baseI;                   \
        float4* eo = (float4*)(out + (OFF)) + baseI;                        \
        _Pragma("unroll")                                                   \
        for (int it = 0; it < JT / 2; it++) {                               \
            const int t = tid + it * 256;                                   \
            float4 cf = scf[it * 2 + xsel];                                 \
            float fv = cf.x, aa = cf.SEL;                                   \
            float4 e  = __ldcs(ein + t);                                    \
            float4 rr;                                                      \
            rr.x = fmaf(e.x, fv, aa * xv.x);                                \
            rr.y = fmaf(e.y, fv, aa * xv.y);                                \
            rr.z = fmaf(e.z, fv, aa * xv.z);                                \
            rr.w = fmaf(e.w, fv, aa * xv.w);                                \
            __stcs(eo + t, rr);                                             \
        }                                                                   \
    }

    TRACE_H(e_ih, OFF_EWIH, y)
    TRACE_H(e_fh, OFF_EWFH, z)
    TRACE_H(e_ch, OFF_EWCH, w)
    TRACE_X(e_ix, OFF_EWIX, y)
    TRACE_X(e_fx, OFF_EWFX, z)
    TRACE_X(e_cx, OFF_EWCX, w)
}

// ---------------------------------------------------------------------------
extern "C" void kernel_launch(void* const* d_in, const int* in_sizes, int n_in,
                              void* d_out, int out_size)
{
    const float* x      = (const float*)d_in[0];
    const float* w_ix   = (const float*)d_in[1];
    const float* w_ih   = (const float*)d_in[2];
    const float* b_i    = (const float*)d_in[3];
    const float* w_fx   = (const float*)d_in[4];
    const float* w_fh   = (const float*)d_in[5];
    const float* b_f    = (const float*)d_in[6];
    const float* w_ox   = (const float*)d_in[7];
    const float* w_oh   = (const float*)d_in[8];
    const float* b_o    = (const float*)d_in[9];
    const float* w_cx   = (const float*)d_in[10];
    const float* w_ch   = (const float*)d_in[11];
    const float* b_c    = (const float*)d_in[12];
    const float* h_last = (const float*)d_in[13];
    const float* c_last = (const float*)d_in[14];
    const float* e_w_ix = (const float*)d_in[15];
    const float* e_w_ih = (const float*)d_in[16];
    const float* e_b_i  = (const float*)d_in[17];
    const float* e_w_fx = (const float*)d_in[18];
    const float* e_w_fh = (const float*)d_in[19];
    const float* e_b_f  = (const float*)d_in[20];
    const float* e_w_cx = (const float*)d_in[21];
    const float* e_w_ch = (const float*)d_in[22];
    const float* e_b_c  = (const float*)d_in[23];
    float* out = (float*)d_out;

    GatePtrs p;
    p.wx[0] = w_ix; p.wx[1] = w_fx; p.wx[2] = w_ox; p.wx[3] = w_cx;
    p.wh[0] = w_ih; p.wh[1] = w_fh; p.wh[2] = w_oh; p.wh[3] = w_ch;

    dim3 g1(HH / 8, 4, NKC);
    gates_kernel<<<g1, 128>>>(x, h_last, p);

    dim3 g3(HH / JT, Bb);
    trace_kernel<<<g3, 256>>>(x, h_last, c_last, b_i, b_f, b_o, b_c,
                              e_b_i, e_b_f, e_b_c,
                              e_w_ix, e_w_ih, e_w_fx, e_w_fh,
                              e_w_cx, e_w_ch, out);
}

// round 11
// speedup vs baseline: 1.0240x; 1.0240x over previous
#include <cuda_runtime.h>
#include <math.h>

#define Bb 16
#define II 512
#define HH 1024
#define BH (Bb*HH)            // 16384
#define NKC 6                 // K-chunks of 256 columns

// Output offsets (floats): h, c, e_w_ix, e_w_ih, e_b_i, e_w_fx, e_w_fh, e_b_f, e_w_cx, e_w_ch, e_b_c
#define OFF_H     0
#define OFF_C     16384
#define OFF_EWIX  32768
#define OFF_EWIH  8421376
#define OFF_EBI   25198592
#define OFF_EWFX  25214976
#define OFF_EWFH  33603584
#define OFF_EBF   50380800
#define OFF_EWCX  50397184
#define OFF_EWCH  58785792
#define OFF_EBC   75563008

// Scratch (no allocation allowed)
__device__ float g_part[NKC][4 * BH];   // partial pre-activations per K-chunk

struct GatePtrs {
    const float* wx[4];
    const float* wh[4];
};

typedef unsigned long long u64;

__device__ __forceinline__ u64 pack2(float lo, float hi) {
    u64 r;
    asm("mov.b64 %0, {%1, %2};" : "=l"(r) : "f"(lo), "f"(hi));
    return r;
}
__device__ __forceinline__ void fma2(u64& acc, u64 a, u64 b) {
    asm("fma.rn.f32x2 %0, %1, %2, %0;" : "+l"(acc) : "l"(a), "l"(b));
}
__device__ __forceinline__ void unpack2(u64 v, float& lo, float& hi) {
    asm("mov.b64 {%0, %1}, %2;" : "=f"(lo), "=f"(hi) : "l"(v));
}

// ---------------------------------------------------------------------------
// Kernel 1: gate pre-activation partials with packed f32x2 FMA.
// grid = (HH/16, 4 gates, 6 K-chunks of 256 cols), block = 128 (4 warps).
// Each warp: 4 j-rows x 16 batches; batches paired into f32x2 lanes ->
// FMA-pipe instruction count halves vs scalar FFMA. No smem, no barriers.
// ---------------------------------------------------------------------------
__global__ __launch_bounds__(128, 4) void gates_kernel(
    const float* __restrict__ x, const float* __restrict__ h_last, GatePtrs p)
{
    const int tid  = threadIdx.x;
    const int warp = tid >> 5;
    const int lane = tid & 31;
    const int kc   = blockIdx.z;
    const int g    = blockIdx.y;
    const int j0   = blockIdx.x * 16 + warp * 4;

    const float* wbase = (kc < 2) ? p.wx[g] : p.wh[g];
    const int rowlen   = (kc < 2) ? II : HH;
    const int koff     = (kc < 2) ? kc * 256 : (kc - 2) * 256;

    const float4* zsrc = (kc < 2) ? (const float4*)x : (const float4*)h_last;
    const int rowf4    = (kc < 2) ? (II / 4) : (HH / 4);
    const int zoff     = (kc < 2) ? kc * 64 : (kc - 2) * 64;

    // acc[r*8+bp] accumulates batches (2bp, 2bp+1) for row j0+r
    u64 acc[32];
#pragma unroll
    for (int m = 0; m < 32; m++) acc[m] = 0ull;

#pragma unroll
    for (int it = 0; it < 2; it++) {
        // Load this it's weights: 4 independent LDG.128
        float4 wr[4];
#pragma unroll
        for (int r = 0; r < 4; r++)
            wr[r] = *((const float4*)(wbase + (size_t)(j0 + r) * rowlen + koff)
                      + it * 32 + lane);

        // Pack weight components as (w,w) pairs — ALU pipe
        u64 w2[4][4];
#pragma unroll
        for (int r = 0; r < 4; r++) {
            w2[r][0] = pack2(wr[r].x, wr[r].x);
            w2[r][1] = pack2(wr[r].y, wr[r].y);
            w2[r][2] = pack2(wr[r].z, wr[r].z);
            w2[r][3] = pack2(wr[r].w, wr[r].w);
        }

        const int k4 = zoff + it * 32 + lane;
#pragma unroll
        for (int bp = 0; bp < 8; bp++) {
            float4 zl = __ldg(zsrc + (2 * bp)     * rowf4 + k4);
            float4 zh = __ldg(zsrc + (2 * bp + 1) * rowf4 + k4);
            u64 z0 = pack2(zl.x, zh.x);
            u64 z1 = pack2(zl.y, zh.y);
            u64 z2 = pack2(zl.z, zh.z);
            u64 z3 = pack2(zl.w, zh.w);
#pragma unroll
            for (int r = 0; r < 4; r++) {
                fma2(acc[r * 8 + bp], w2[r][0], z0);
                fma2(acc[r * 8 + bp], w2[r][1], z1);
                fma2(acc[r * 8 + bp], w2[r][2], z2);
                fma2(acc[r * 8 + bp], w2[r][3], z3);
            }
        }
    }

    // Unpack to 64 scalars: a[r*16 + b]
    float a[64];
#pragma unroll
    for (int r = 0; r < 4; r++)
#pragma unroll
        for (int bp = 0; bp < 8; bp++)
            unpack2(acc[r * 8 + bp], a[r * 16 + 2 * bp], a[r * 16 + 2 * bp + 1]);

    // Multi-value butterfly reduction: 64 values -> 2 per lane (62 shuffles).
#pragma unroll
    for (int k = 0; k < 5; k++) {
        const int d = 1 << k;
        const int n = 64 >> k;
        const bool hi = (lane >> k) & 1;
#pragma unroll
        for (int m = 0; m < 32; m++) {
            if (m < n / 2) {
                float mine = hi ? a[m] : a[m + n / 2];
                float got  = __shfl_xor_sync(0xffffffffu, mine, d);
                a[m] = (hi ? a[m + n / 2] : a[m]) + got;
            }
        }
    }

    // lane L holds value indices v = (bitrev5(L) << 1) | j for j in {0,1}
    const unsigned rev = __brev((unsigned)lane) >> 27;
#pragma unroll
    for (int j = 0; j < 2; j++) {
        const unsigned v = (rev << 1) | j;
        const int jj = v >> 4;
        const int b  = v & 15;
        g_part[kc][g * BH + b * HH + j0 + jj] = a[j];
    }
}

// ---------------------------------------------------------------------------
// Kernel 2: fused pointwise + HBM-bound trace update (unchanged; measured
// 5.9 TB/s four rounds running — at the mixed R/W HBM ceiling).
// ---------------------------------------------------------------------------
#define JT 16

__global__ __launch_bounds__(256) void trace_kernel(
    const float* __restrict__ x, const float* __restrict__ h_last,
    const float* __restrict__ c_last,
    const float* __restrict__ b_i, const float* __restrict__ b_f,
    const float* __restrict__ b_o, const float* __restrict__ b_c,
    const float* __restrict__ eb_i, const float* __restrict__ eb_f,
    const float* __restrict__ eb_c,
    const float* __restrict__ e_ix, const float* __restrict__ e_ih,
    const float* __restrict__ e_fx, const float* __restrict__ e_fh,
    const float* __restrict__ e_cx, const float* __restrict__ e_ch,
    float* __restrict__ out)
{
    __shared__ float4 sx[II / 4];   // 2KB
    __shared__ float4 sh[HH / 4];   // 4KB
    __shared__ float4 scf[JT];

    const int tid = threadIdx.x;
    const int b   = blockIdx.y;
    const int j0  = blockIdx.x * JT;

    if (tid < 128) sx[tid] = ((const float4*)(x + b * II))[tid];
    sh[tid] = ((const float4*)(h_last + b * HH))[tid];

    if (tid < JT) {
        const int j   = j0 + tid;
        const int idx = b * HH + j;

        float pi = b_i[j], pf = b_f[j], po = b_o[j], pc = b_c[j];
#pragma unroll
        for (int c = 0; c < NKC; c++) {
            pi += g_part[c][0 * BH + idx];
            pf += g_part[c][1 * BH + idx];
            po += g_part[c][2 * BH + idx];
            pc += g_part[c][3 * BH + idx];
        }

        float i  = 1.f / (1.f + expf(-pi));
        float f  = 1.f / (1.f + expf(-pf));
        float o  = 1.f / (1.f + expf(-po));
        float ch = tanhf(pc);
        float cl = c_last[idx];

        float c = fmaf(f, cl, i * ch);
        float h = o * c;
        float di  = i * (1.f - i);
        float df  = f * (1.f - f);
        float dch = 1.f - ch * ch;
        float ai = di * ch;
        float af = df * cl;
        float ac = dch * i;

        out[OFF_H + idx]   = h;
        out[OFF_C + idx]   = c;
        out[OFF_EBI + idx] = fmaf(eb_i[idx], f, ai);
        out[OFF_EBF + idx] = fmaf(eb_f[idx], f, af);
        out[OFF_EBC + idx] = fmaf(eb_c[idx], f, ac);
        scf[tid] = make_float4(f, ai, af, ac);
    }
    __syncthreads();

    const size_t baseH = (size_t)(b * HH + j0) * (HH / 4);
    const size_t baseI = (size_t)(b * HH + j0) * (II / 4);

    const float4 hv = sh[tid];
    const float4 xv = sx[tid & 127];
    const int xsel = tid >> 7;

#define TRACE_H(SRC, OFF, SEL)                                              \
    {                                                                       \
        const float4* ein = (const float4*)(SRC) + baseH;                   \
        float4* eo = (float4*)(out + (OFF)) + baseH;                        \
        _Pragma("unroll")                                                   \
        for (int it = 0; it < JT; it++) {                                   \
            const int t = tid + it * 256;                                   \
            float4 cf = scf[it];                                            \
            float fv = cf.x, aa = cf.SEL;                                   \
            float4 e  = __ldcs(ein + t);                                    \
            float4 rr;                                                      \
            rr.x = fmaf(e.x, fv, aa * hv.x);                                \
            rr.y = fmaf(e.y, fv, aa * hv.y);                                \
            rr.z = fmaf(e.z, fv, aa * hv.z);                                \
            rr.w = fmaf(e.w, fv, aa * hv.w);                                \
            __stcs(eo + t, rr);                                             \
        }                                                                   \
    }

#define TRACE_X(SRC, OFF, SEL)                                              \
    {                                                                       \
        const float4* ein = (const float4*)(SRC) + baseI;                   \
        float4* eo = (float4*)(out + (OFF)) + baseI;                        \
        _Pragma("unroll")                                                   \
        for (int it = 0; it < JT / 2; it++) {                               \
            const int t = tid + it * 256;                                   \
            float4 cf = scf[it * 2 + xsel];                                 \
            float fv = cf.x, aa = cf.SEL;                                   \
            float4 e  = __ldcs(ein + t);                                    \
            float4 rr;                                                      \
            rr.x = fmaf(e.x, fv, aa * xv.x);                                \
            rr.y = fmaf(e.y, fv, aa * xv.y);                                \
            rr.z = fmaf(e.z, fv, aa * xv.z);                                \
            rr.w = fmaf(e.w, fv, aa * xv.w);                                \
            __stcs(eo + t, rr);                                             \
        }                                                                   \
    }

    TRACE_H(e_ih, OFF_EWIH, y)
    TRACE_H(e_fh, OFF_EWFH, z)
    TRACE_H(e_ch, OFF_EWCH, w)
    TRACE_X(e_ix, OFF_EWIX, y)
    TRACE_X(e_fx, OFF_EWFX, z)
    TRACE_X(e_cx, OFF_EWCX, w)
}

// ---------------------------------------------------------------------------
extern "C" void kernel_launch(void* const* d_in, const int* in_sizes, int n_in,
                              void* d_out, int out_size)
{
    const float* x      = (const float*)d_in[0];
    const float* w_ix   = (const float*)d_in[1];
    const float* w_ih   = (const float*)d_in[2];
    const float* b_i    = (const float*)d_in[3];
    const float* w_fx   = (const float*)d_in[4];
    const float* w_fh   = (const float*)d_in[5];
    const float* b_f    = (const float*)d_in[6];
    const float* w_ox   = (const float*)d_in[7];
    const float* w_oh   = (const float*)d_in[8];
    const float* b_o    = (const float*)d_in[9];
    const float* w_cx   = (const float*)d_in[10];
    const float* w_ch   = (const float*)d_in[11];
    const float* b_c    = (const float*)d_in[12];
    const float* h_last = (const float*)d_in[13];
    const float* c_last = (const float*)d_in[14];
    const float* e_w_ix = (const float*)d_in[15];
    const float* e_w_ih = (const float*)d_in[16];
    const float* e_b_i  = (const float*)d_in[17];
    const float* e_w_fx = (const float*)d_in[18];
    const float* e_w_fh = (const float*)d_in[19];
    const float* e_b_f  = (const float*)d_in[20];
    const float* e_w_cx = (const float*)d_in[21];
    const float* e_w_ch = (const float*)d_in[22];
    const float* e_b_c  = (const float*)d_in[23];
    float* out = (float*)d_out;

    GatePtrs p;
    p.wx[0] = w_ix; p.wx[1] = w_fx; p.wx[2] = w_ox; p.wx[3] = w_cx;
    p.wh[0] = w_ih; p.wh[1] = w_fh; p.wh[2] = w_oh; p.wh[3] = w_ch;

    dim3 g1(HH / 16, 4, NKC);
    gates_kernel<<<g1, 128>>>(x, h_last, p);

    dim3 g3(HH / JT, Bb);
    trace_kernel<<<g3, 256>>>(x, h_last, c_last, b_i, b_f, b_o, b_c,
                              e_b_i, e_b_f, e_b_c,
                              e_w_ix, e_w_ih, e_w_fx, e_w_fh,
                              e_w_cx, e_w_ch, out);
}